// round 12
// baseline (speedup 1.0000x reference)
#include <cuda_runtime.h>
#include <cstdint>

// Problem constants (fixed by the reference: SHAPE = (8192, 4096), P = 0.3)
#define N_ELEMS   (8192 * 4096)        // 33,554,432 floats
#define N_WORDS   (N_ELEMS / 32)       // 1,048,576 uint32 mask words = 4 MB
#define N_FLOAT4  (N_ELEMS / 4)        // 8,388,608 float4s
#define HALF_ELEMS (N_ELEMS / 2)       // 16,777,216 : split point
#define HALF_F4    (N_FLOAT4 / 2)      // 4,194,304 float4s per half

// Scratch: 1 bit per element. Zero at module load; the apply phases re-zero
// their half every pass for the next graph replay (self-cleaning).
__device__ uint32_t g_mask[N_WORDS];

__device__ __forceinline__ void red_or_bit(unsigned int a) {
    atomicOr(&g_mask[a >> 5], 1u << (a & 31));
}

// ---------------------------------------------------------------------------
// Shared apply body: copy + masked zero + self-clean for 1024 consecutive
// float4s starting at f4_base + blockIdx.x*1024 (coalesced, ILP=4).
// 8 adjacent same-warp threads share one mask word; (tid&7)==0 lane cleans
// AFTER the group's loads (same warp -> program order, race-free).
// ---------------------------------------------------------------------------
__device__ __forceinline__ void apply_body(const float4* __restrict__ X,
                                           float4* __restrict__ out,
                                           int f4_base) {
    int tid = threadIdx.x;
    int base = f4_base + blockIdx.x * 1024 + tid;
    int i0 = base, i1 = base + 256, i2 = base + 512, i3 = base + 768;

    uint32_t w0 = g_mask[i0 >> 3];
    uint32_t w1 = g_mask[i1 >> 3];
    uint32_t w2 = g_mask[i2 >> 3];
    uint32_t w3 = g_mask[i3 >> 3];
    float4 v0 = __ldcs(&X[i0]);
    float4 v1 = __ldcs(&X[i1]);
    float4 v2 = __ldcs(&X[i2]);
    float4 v3 = __ldcs(&X[i3]);

    uint32_t n0 = w0 >> ((i0 & 7) * 4);
    if (n0 & 1u) v0.x = 0.0f;
    if (n0 & 2u) v0.y = 0.0f;
    if (n0 & 4u) v0.z = 0.0f;
    if (n0 & 8u) v0.w = 0.0f;
    __stcs(&out[i0], v0);

    uint32_t n1 = w1 >> ((i1 & 7) * 4);
    if (n1 & 1u) v1.x = 0.0f;
    if (n1 & 2u) v1.y = 0.0f;
    if (n1 & 4u) v1.z = 0.0f;
    if (n1 & 8u) v1.w = 0.0f;
    __stcs(&out[i1], v1);

    uint32_t n2 = w2 >> ((i2 & 7) * 4);
    if (n2 & 1u) v2.x = 0.0f;
    if (n2 & 2u) v2.y = 0.0f;
    if (n2 & 4u) v2.z = 0.0f;
    if (n2 & 8u) v2.w = 0.0f;
    __stcs(&out[i2], v2);

    uint32_t n3 = w3 >> ((i3 & 7) * 4);
    if (n3 & 1u) v3.x = 0.0f;
    if (n3 & 2u) v3.y = 0.0f;
    if (n3 & 4u) v3.z = 0.0f;
    if (n3 & 8u) v3.w = 0.0f;
    __stcs(&out[i3], v3);

    if ((tid & 7) == 0) {
        g_mask[i0 >> 3] = 0u;
        g_mask[i1 >> 3] = 0u;
        g_mask[i2 >> 3] = 0u;
        g_mask[i3 >> 3] = 0u;
    }
}

// ---------------------------------------------------------------------------
// K1: scatter bits for half A (idx < HALF_ELEMS). Flat, one int4/thread,
// predicated REDs (inactive lanes generate no wavefronts). Thread 0 also
// handles the scalar tail for half A.
// ---------------------------------------------------------------------------
__global__ void scatter_A_kernel(const int4* __restrict__ idx4, int n_quads,
                                 int k) {
    int i = blockIdx.x * blockDim.x + threadIdx.x;
    if (i < n_quads) {
        int4 v = __ldcs(&idx4[i]);
        unsigned int a = (unsigned int)v.x, b = (unsigned int)v.y;
        unsigned int c = (unsigned int)v.z, d = (unsigned int)v.w;
        if (a < HALF_ELEMS) red_or_bit(a);
        if (b < HALF_ELEMS) red_or_bit(b);
        if (c < HALF_ELEMS) red_or_bit(c);
        if (d < HALF_ELEMS) red_or_bit(d);
    }
    if (i == 0) {
        const int* idx = (const int*)idx4;
        for (int j = n_quads * 4; j < k; j++) {
            unsigned int a = (unsigned int)idx[j];
            if (a < HALF_ELEMS) red_or_bit(a);
        }
    }
}

// ---------------------------------------------------------------------------
// K2 (fused): apply half A (DRAM-bound) + scatter half B (L1tex-bound).
// The scatter REDs are fire-and-forget and soak up LSU issue slots while the
// apply's streaming loads/stores round-trip to DRAM. Grid = HALF_F4/1024
// blocks of 256; each thread also grid-strides over ~2.4 idx quads.
// ---------------------------------------------------------------------------
__global__ void __launch_bounds__(256)
fused_applyA_scatterB_kernel(const float4* __restrict__ X,
                             float4* __restrict__ out,
                             const int4* __restrict__ idx4, int n_quads,
                             int k) {
    // scatter half B (issue first: fire-and-forget fills the pipe)
    int t = blockIdx.x * 256 + threadIdx.x;
    const int nthreads = (HALF_F4 / 1024) * 256;   // 1,048,576
    for (int q = t; q < n_quads; q += nthreads) {
        int4 v = __ldcs(&idx4[q]);
        unsigned int a = (unsigned int)v.x, b = (unsigned int)v.y;
        unsigned int c = (unsigned int)v.z, d = (unsigned int)v.w;
        if (a >= HALF_ELEMS) red_or_bit(a);
        if (b >= HALF_ELEMS) red_or_bit(b);
        if (c >= HALF_ELEMS) red_or_bit(c);
        if (d >= HALF_ELEMS) red_or_bit(d);
    }
    if (t == 0) {
        const int* idx = (const int*)idx4;
        for (int j = n_quads * 4; j < k; j++) {
            unsigned int a = (unsigned int)idx[j];
            if (a >= HALF_ELEMS) red_or_bit(a);
        }
    }

    // apply half A
    apply_body(X, out, 0);
}

// ---------------------------------------------------------------------------
// K3: apply half B.
// ---------------------------------------------------------------------------
__global__ void __launch_bounds__(256)
apply_B_kernel(const float4* __restrict__ X, float4* __restrict__ out) {
    apply_body(X, out, HALF_F4);
}

extern "C" void kernel_launch(void* const* d_in, const int* in_sizes, int n_in,
                              void* d_out, int out_size) {
    const float* X = (const float*)d_in[0];
    const int* drop_idx = (const int*)d_in[1];   // JAX x64-disabled => int32
    int k = in_sizes[1];                          // number of indices
    float* out = (float*)d_out;

    int n_quads = k / 4;

    // K1: scatter half-A bits (mask zero: module init or previous applies)
    {
        int threads = 256;
        int blocks = (n_quads + threads - 1) / threads;
        scatter_A_kernel<<<blocks, threads>>>((const int4*)drop_idx, n_quads,
                                              k);
    }

    // K2: apply half A || scatter half B (fused overlap)
    fused_applyA_scatterB_kernel<<<HALF_F4 / 1024, 256>>>(
        (const float4*)X, (float4*)out, (const int4*)drop_idx, n_quads, k);

    // K3: apply half B
    apply_B_kernel<<<HALF_F4 / 1024, 256>>>((const float4*)X, (float4*)out);
}

// round 13
// speedup vs baseline: 1.0219x; 1.0219x over previous
#include <cuda_runtime.h>
#include <cstdint>

// Problem constants (fixed by the reference: SHAPE = (8192, 4096), P = 0.3)
#define N_ELEMS   (8192 * 4096)        // 33,554,432 floats
#define N_WORDS   (N_ELEMS / 32)       // 1,048,576 uint32 mask words = 4 MB
#define N_FLOAT4  (N_ELEMS / 4)        // 8,388,608 float4s

// Region split: A = first 5/8 of the tensor (chosen so A_F4 % 768 == 0 and
// B_F4 % 1024 == 0). K1 scatters A, K2 applies A while scattering B, K3
// applies B.
#define A_F4      5240832              // float4s in region A
#define B_F4      (N_FLOAT4 - A_F4)    // 3,147,776
#define SPLIT     (A_F4 * 4)           // 20,963,328 elements
#define K2_BLOCKS (A_F4 / 768)         // 6824
#define K3_BLOCKS (B_F4 / 1024)        // 3074

// Scratch: 1 bit per element. Zero at module load; the apply phases re-zero
// their region every pass for the next graph replay (self-cleaning).
__device__ uint32_t g_mask[N_WORDS];

__device__ __forceinline__ void red_or_bit(unsigned int a) {
    atomicOr(&g_mask[a >> 5], 1u << (a & 31));
}

// ---------------------------------------------------------------------------
// K1: scatter bits for region A (idx < SPLIT). Flat, one int4/thread,
// predicated REDs (inactive lanes generate no wavefronts). Thread 0 also
// handles the scalar tail for region A.
// ---------------------------------------------------------------------------
__global__ void scatter_A_kernel(const int4* __restrict__ idx4, int n_quads,
                                 int k) {
    int i = blockIdx.x * blockDim.x + threadIdx.x;
    if (i < n_quads) {
        int4 v = __ldcs(&idx4[i]);
        unsigned int a = (unsigned int)v.x, b = (unsigned int)v.y;
        unsigned int c = (unsigned int)v.z, d = (unsigned int)v.w;
        if (a < SPLIT) red_or_bit(a);
        if (b < SPLIT) red_or_bit(b);
        if (c < SPLIT) red_or_bit(c);
        if (d < SPLIT) red_or_bit(d);
    }
    if (i == 0) {
        const int* idx = (const int*)idx4;
        for (int j = n_quads * 4; j < k; j++) {
            unsigned int a = (unsigned int)idx[j];
            if (a < SPLIT) red_or_bit(a);
        }
    }
}

// ---------------------------------------------------------------------------
// K2 (warp-specialized fusion): warps 0-5 apply region A (DRAM-bound,
// coalesced ILP=4, 768 float4s per block); warps 6-7 scatter region B
// (L1tex-wavefront-bound, grid-stride with 2-wide unrolled idx loads).
// Roles never share a warp, so neither blocks the other's issue; the SM
// scheduler interleaves apply's streaming loads with scatter's REDs.
// Mask disjointness: apply touches only words < SPLIT/32, scatter REDs only
// words >= SPLIT/32.
// ---------------------------------------------------------------------------
__global__ void __launch_bounds__(256)
fused_applyA_scatterB_kernel(const float4* __restrict__ X,
                             float4* __restrict__ out,
                             const int4* __restrict__ idx4, int n_quads,
                             int k) {
    int tid = threadIdx.x;

    if (tid < 192) {
        // ---- apply region A: 768 consecutive float4s per block ----
        int base = blockIdx.x * 768 + tid;
        int i0 = base, i1 = base + 192, i2 = base + 384, i3 = base + 576;

        uint32_t w0 = g_mask[i0 >> 3];
        uint32_t w1 = g_mask[i1 >> 3];
        uint32_t w2 = g_mask[i2 >> 3];
        uint32_t w3 = g_mask[i3 >> 3];
        float4 v0 = __ldcs(&X[i0]);
        float4 v1 = __ldcs(&X[i1]);
        float4 v2 = __ldcs(&X[i2]);
        float4 v3 = __ldcs(&X[i3]);

        uint32_t n0 = w0 >> ((i0 & 7) * 4);
        if (n0 & 1u) v0.x = 0.0f;
        if (n0 & 2u) v0.y = 0.0f;
        if (n0 & 4u) v0.z = 0.0f;
        if (n0 & 8u) v0.w = 0.0f;
        __stcs(&out[i0], v0);

        uint32_t n1 = w1 >> ((i1 & 7) * 4);
        if (n1 & 1u) v1.x = 0.0f;
        if (n1 & 2u) v1.y = 0.0f;
        if (n1 & 4u) v1.z = 0.0f;
        if (n1 & 8u) v1.w = 0.0f;
        __stcs(&out[i1], v1);

        uint32_t n2 = w2 >> ((i2 & 7) * 4);
        if (n2 & 1u) v2.x = 0.0f;
        if (n2 & 2u) v2.y = 0.0f;
        if (n2 & 4u) v2.z = 0.0f;
        if (n2 & 8u) v2.w = 0.0f;
        __stcs(&out[i2], v2);

        uint32_t n3 = w3 >> ((i3 & 7) * 4);
        if (n3 & 1u) v3.x = 0.0f;
        if (n3 & 2u) v3.y = 0.0f;
        if (n3 & 4u) v3.z = 0.0f;
        if (n3 & 8u) v3.w = 0.0f;
        __stcs(&out[i3], v3);

        // self-clean region-A words (same-warp readers -> race-free)
        if ((tid & 7) == 0) {
            g_mask[i0 >> 3] = 0u;
            g_mask[i1 >> 3] = 0u;
            g_mask[i2 >> 3] = 0u;
            g_mask[i3 >> 3] = 0u;
        }
    } else {
        // ---- scatter region B (idx >= SPLIT) ----
        int t = blockIdx.x * 64 + (tid - 192);
        const int nscatter = K2_BLOCKS * 64;        // 436,736 threads
        int q = t;
        for (; q + nscatter < n_quads; q += 2 * nscatter) {
            int4 u = __ldcs(&idx4[q]);
            int4 v = __ldcs(&idx4[q + nscatter]);
            unsigned int a0 = (unsigned int)u.x, a1 = (unsigned int)u.y;
            unsigned int a2 = (unsigned int)u.z, a3 = (unsigned int)u.w;
            unsigned int b0 = (unsigned int)v.x, b1 = (unsigned int)v.y;
            unsigned int b2 = (unsigned int)v.z, b3 = (unsigned int)v.w;
            if (a0 >= SPLIT) red_or_bit(a0);
            if (a1 >= SPLIT) red_or_bit(a1);
            if (a2 >= SPLIT) red_or_bit(a2);
            if (a3 >= SPLIT) red_or_bit(a3);
            if (b0 >= SPLIT) red_or_bit(b0);
            if (b1 >= SPLIT) red_or_bit(b1);
            if (b2 >= SPLIT) red_or_bit(b2);
            if (b3 >= SPLIT) red_or_bit(b3);
        }
        if (q < n_quads) {
            int4 u = __ldcs(&idx4[q]);
            unsigned int a0 = (unsigned int)u.x, a1 = (unsigned int)u.y;
            unsigned int a2 = (unsigned int)u.z, a3 = (unsigned int)u.w;
            if (a0 >= SPLIT) red_or_bit(a0);
            if (a1 >= SPLIT) red_or_bit(a1);
            if (a2 >= SPLIT) red_or_bit(a2);
            if (a3 >= SPLIT) red_or_bit(a3);
        }
        if (t == 0) {
            const int* idx = (const int*)idx4;
            for (int j = n_quads * 4; j < k; j++) {
                unsigned int a = (unsigned int)idx[j];
                if (a >= SPLIT) red_or_bit(a);
            }
        }
    }
}

// ---------------------------------------------------------------------------
// K3: apply region B (1024 consecutive float4s per 256-thread block).
// ---------------------------------------------------------------------------
__global__ void __launch_bounds__(256)
apply_B_kernel(const float4* __restrict__ X, float4* __restrict__ out) {
    int tid = threadIdx.x;
    int base = A_F4 + blockIdx.x * 1024 + tid;
    int i0 = base, i1 = base + 256, i2 = base + 512, i3 = base + 768;

    uint32_t w0 = g_mask[i0 >> 3];
    uint32_t w1 = g_mask[i1 >> 3];
    uint32_t w2 = g_mask[i2 >> 3];
    uint32_t w3 = g_mask[i3 >> 3];
    float4 v0 = __ldcs(&X[i0]);
    float4 v1 = __ldcs(&X[i1]);
    float4 v2 = __ldcs(&X[i2]);
    float4 v3 = __ldcs(&X[i3]);

    uint32_t n0 = w0 >> ((i0 & 7) * 4);
    if (n0 & 1u) v0.x = 0.0f;
    if (n0 & 2u) v0.y = 0.0f;
    if (n0 & 4u) v0.z = 0.0f;
    if (n0 & 8u) v0.w = 0.0f;
    __stcs(&out[i0], v0);

    uint32_t n1 = w1 >> ((i1 & 7) * 4);
    if (n1 & 1u) v1.x = 0.0f;
    if (n1 & 2u) v1.y = 0.0f;
    if (n1 & 4u) v1.z = 0.0f;
    if (n1 & 8u) v1.w = 0.0f;
    __stcs(&out[i1], v1);

    uint32_t n2 = w2 >> ((i2 & 7) * 4);
    if (n2 & 1u) v2.x = 0.0f;
    if (n2 & 2u) v2.y = 0.0f;
    if (n2 & 4u) v2.z = 0.0f;
    if (n2 & 8u) v2.w = 0.0f;
    __stcs(&out[i2], v2);

    uint32_t n3 = w3 >> ((i3 & 7) * 4);
    if (n3 & 1u) v3.x = 0.0f;
    if (n3 & 2u) v3.y = 0.0f;
    if (n3 & 4u) v3.z = 0.0f;
    if (n3 & 8u) v3.w = 0.0f;
    __stcs(&out[i3], v3);

    if ((tid & 7) == 0) {
        g_mask[i0 >> 3] = 0u;
        g_mask[i1 >> 3] = 0u;
        g_mask[i2 >> 3] = 0u;
        g_mask[i3 >> 3] = 0u;
    }
}

extern "C" void kernel_launch(void* const* d_in, const int* in_sizes, int n_in,
                              void* d_out, int out_size) {
    const float* X = (const float*)d_in[0];
    const int* drop_idx = (const int*)d_in[1];   // JAX x64-disabled => int32
    int k = in_sizes[1];                          // number of indices
    float* out = (float*)d_out;

    int n_quads = k / 4;

    // K1: scatter region-A bits (mask zero: module init or previous applies)
    {
        int threads = 256;
        int blocks = (n_quads + threads - 1) / threads;
        scatter_A_kernel<<<blocks, threads>>>((const int4*)drop_idx, n_quads,
                                              k);
    }

    // K2: apply region A || scatter region B (warp-specialized)
    fused_applyA_scatterB_kernel<<<K2_BLOCKS, 256>>>(
        (const float4*)X, (float4*)out, (const int4*)drop_idx, n_quads, k);

    // K3: apply region B
    apply_B_kernel<<<K3_BLOCKS, 256>>>((const float4*)X, (float4*)out);
}